// round 7
// baseline (speedup 1.0000x reference)
#include <cuda_runtime.h>

#define NN 1024
#define DD 128

// ---------------------------------------------------------------------------
// Device scratch (allocation-free)
// ---------------------------------------------------------------------------
__device__ float g_PIBT[DD * NN];   // pi + b1, transposed [d][i]
__device__ float g_PJT [DD * NN];   // pj,      transposed [d][j]
__device__ float g_W2H [DD];        // 0.5 * W2
__device__ float g_ci  [NN];        // 0.5 * (pi+b1)[i,:] . W2
__device__ float g_cj  [NN];        // 0.5 * pj[j,:]     . W2

// ---------------------------------------------------------------------------
// f32x2 packed helpers (sm_103a)
// ---------------------------------------------------------------------------
__device__ __forceinline__ unsigned long long pack2(float lo, float hi) {
    unsigned long long r;
    asm("mov.b64 %0, {%1, %2};" : "=l"(r) : "f"(lo), "f"(hi));
    return r;
}
__device__ __forceinline__ void unpack2(unsigned long long v, float& lo, float& hi) {
    asm("mov.b64 {%0, %1}, %2;" : "=f"(lo), "=f"(hi) : "l"(v));
}
__device__ __forceinline__ unsigned long long add2(unsigned long long a, unsigned long long b) {
    unsigned long long r;
    asm("add.rn.f32x2 %0, %1, %2;" : "=l"(r) : "l"(a), "l"(b));
    return r;
}
__device__ __forceinline__ unsigned long long fma2(unsigned long long a, unsigned long long b,
                                                   unsigned long long c) {
    unsigned long long r;
    asm("fma.rn.f32x2 %0, %1, %2, %3;" : "=l"(r) : "l"(a), "l"(b), "l"(c));
    return r;
}
#define ABS2_MASK 0x7FFFFFFF7FFFFFFFULL

// ---------------------------------------------------------------------------
// Kernel A (v4): fused GEMM + transpose + ci/cj, all in one kernel.
// 128 blocks x 512 threads. Block = 8 i-rows x 256 output columns.
// Main loop: thread = (dc4 = tid&63 -> 4 consecutive cols via LDG.128,
//                      h = tid>>6  -> 1 row). 4 accumulators, unroll 8
//            -> 8 independent 16B W1 loads in flight (MLP=8).
// Epilogue: results staged in smem ts[8][260]; warps 0-7 write coalesced
//           float4 transposed stores; warps 8-15 compute ci/cj for the
//           block's 8 rows (replaces the former cicj kernel).
// ---------------------------------------------------------------------------
__global__ void __launch_bounds__(512, 1) prep_kernel(
    const float* __restrict__ z, const float* __restrict__ W1,
    const float* __restrict__ b1, const float* __restrict__ W2)
{
    __shared__ float zs[8][DD];
    __shared__ float ts[8][260];         // [row][col 0..255], padded

    const int tid = threadIdx.x;         // 0..511
    const int dc4 = tid & 63;            // 4-column group (0..63)
    const int h   = tid >> 6;            // row within block (0..7)
    const int i0  = blockIdx.x * 8;

    if (blockIdx.x == 0 && tid < DD) g_W2H[tid] = 0.5f * W2[tid];

    if (tid < 256)
        ((float4*)zs)[tid] = ((const float4*)(z + i0 * DD))[tid];
    __syncthreads();

    const int c0 = dc4 * 4;              // global concat column (0..252)
    const float* wp = (c0 < DD) ? (W1 + c0) : (W1 + DD * DD + (c0 - DD));

    float a0 = 0.f, a1 = 0.f, a2 = 0.f, a3 = 0.f;

    #pragma unroll 8
    for (int k = 0; k < DD; k++) {
        const float4 w = __ldg((const float4*)(wp + k * DD));
        const float zv = zs[h][k];       // broadcast: whole warp same addr
        a0 = fmaf(zv, w.x, a0);
        a1 = fmaf(zv, w.y, a1);
        a2 = fmaf(zv, w.z, a2);
        a3 = fmaf(zv, w.w, a3);
    }

    if (c0 < DD) {                       // pi half: add b1
        const float4 bb = *(const float4*)&b1[c0];
        a0 += bb.x; a1 += bb.y; a2 += bb.z; a3 += bb.w;
    }
    *(float4*)&ts[h][c0] = make_float4(a0, a1, a2, a3);
    __syncthreads();

    if (tid < 256) {
        // Transposed stores: thread = (d, array); 8 i-values contiguous
        const int d   = tid & 127;
        const int arr = tid >> 7;        // 0 = PIBT, 1 = PJT
        const int cc  = arr * DD + d;
        float4 lo, hi;
        lo.x = ts[0][cc]; lo.y = ts[1][cc]; lo.z = ts[2][cc]; lo.w = ts[3][cc];
        hi.x = ts[4][cc]; hi.y = ts[5][cc]; hi.z = ts[6][cc]; hi.w = ts[7][cc];
        float* dst = arr ? g_PJT : g_PIBT;
        *(float4*)&dst[d * NN + i0]     = lo;
        *(float4*)&dst[d * NN + i0 + 4] = hi;
    } else {
        // ci/cj: warp w (0..7) handles row w; lane covers 4 cols of each half
        const int t    = tid - 256;
        const int row  = t >> 5;
        const int lane = t & 31;
        float4 w2v = *(const float4*)&W2[lane * 4];
        w2v.x *= 0.5f; w2v.y *= 0.5f; w2v.z *= 0.5f; w2v.w *= 0.5f;
        const float4 piv = *(const float4*)&ts[row][lane * 4];
        const float4 pjv = *(const float4*)&ts[row][DD + lane * 4];
        float si = piv.x * w2v.x + piv.y * w2v.y + piv.z * w2v.z + piv.w * w2v.w;
        float sj = pjv.x * w2v.x + pjv.y * w2v.y + pjv.z * w2v.z + pjv.w * w2v.w;
        #pragma unroll
        for (int off = 16; off; off >>= 1) {
            si += __shfl_down_sync(0xFFFFFFFFu, si, off);
            sj += __shfl_down_sync(0xFFFFFFFFu, sj, off);
        }
        if (lane == 0) {
            g_ci[i0 + row] = si;
            g_cj[i0 + row] = sj;
        }
    }
}

// ---------------------------------------------------------------------------
// Kernel C: q[i,j] = ci[i] + cj[j] + sum_d w'_d * |PIBT[d,i] + PJT[d,j]| + b2
// Tile 64i x 64j per block, 256 threads (16x16), 4i x 4j per thread.
// i-pairs packed in f32x2; all inner loads from smem (conflict-free vectors).
// ---------------------------------------------------------------------------
#define TPAD 68   // row stride in floats (64 + 4), keeps 16B alignment

__global__ void __launch_bounds__(256) pair_kernel(
    const float* __restrict__ b2, float* __restrict__ out)
{
    extern __shared__ float smem[];
    float* pisT = smem;                         // [128][TPAD]
    float* pjs  = smem + DD * TPAD;             // [128][TPAD]
    unsigned long long* w2p =
        (unsigned long long*)(smem + 2 * DD * TPAD);  // [128] packed {w',w'}

    const int tx  = threadIdx.x;                // 0..15 -> 4 j
    const int ty  = threadIdx.y;                // 0..15 -> 4 i
    const int tid = ty * 16 + tx;
    const int ib  = blockIdx.y * 64;
    const int jb  = blockIdx.x * 64;

    // Stage tiles: [128 d][64] each, float4 coalesced, conflict-free STS
    for (int idx = tid; idx < DD * 16; idx += 256) {
        const int d = idx >> 4;
        const int q = idx & 15;
        *(float4*)&pisT[d * TPAD + q * 4] =
            *(const float4*)&g_PIBT[d * NN + ib + q * 4];
        *(float4*)&pjs [d * TPAD + q * 4] =
            *(const float4*)&g_PJT [d * NN + jb + q * 4];
    }
    if (tid < DD) {
        const float w = g_W2H[tid];
        w2p[tid] = pack2(w, w);
    }
    __syncthreads();

    const int i0 = ty * 4;                      // local i base
    const int j0 = tx * 4;                      // local j base

    unsigned long long acc[2][4];               // [i-pair][j] ; pair = (i, i+1)
    #pragma unroll
    for (int p = 0; p < 2; p++)
        #pragma unroll
        for (int j = 0; j < 4; j++) acc[p][j] = 0ULL;

    #pragma unroll 4
    for (int d = 0; d < DD; d++) {
        // A: two natural f32x2 pairs {a(i0),a(i0+1)}, {a(i0+2),a(i0+3)}
        const ulonglong2 aA = *(const ulonglong2*)&pisT[d * TPAD + i0];
        // B: 4 j values, broadcast-packed
        const float4 bf = *(const float4*)&pjs[d * TPAD + j0];
        const unsigned long long bp[4] = {
            pack2(bf.x, bf.x), pack2(bf.y, bf.y),
            pack2(bf.z, bf.z), pack2(bf.w, bf.w) };
        const unsigned long long wd = w2p[d];

        #pragma unroll
        for (int j = 0; j < 4; j++) {
            unsigned long long t0 = add2(aA.x, bp[j]) & ABS2_MASK;
            acc[0][j] = fma2(wd, t0, acc[0][j]);
            unsigned long long t1 = add2(aA.y, bp[j]) & ABS2_MASK;
            acc[1][j] = fma2(wd, t1, acc[1][j]);
        }
    }

    // Epilogue: unpack, add rank-1 terms + b2, vector store
    const float4 civ = *(const float4*)&g_ci[ib + i0];
    const float4 cjv = *(const float4*)&g_cj[jb + j0];
    const float  bb  = __ldg(b2);
    const float  cia[4] = { civ.x, civ.y, civ.z, civ.w };
    const float  cja[4] = { cjv.x, cjv.y, cjv.z, cjv.w };

    float v[4][4];                              // [local i][j]
    #pragma unroll
    for (int p = 0; p < 2; p++)
        #pragma unroll
        for (int j = 0; j < 4; j++) {
            float lo, hi;
            unpack2(acc[p][j], lo, hi);
            v[2 * p][j]     = lo;
            v[2 * p + 1][j] = hi;
        }

    #pragma unroll
    for (int r = 0; r < 4; r++) {
        const float base = cia[r] + bb;
        float4 o;
        o.x = v[r][0] + cja[0] + base;
        o.y = v[r][1] + cja[1] + base;
        o.z = v[r][2] + cja[2] + base;
        o.w = v[r][3] + cja[3] + base;
        *(float4*)&out[(ib + i0 + r) * NN + jb + j0] = o;
    }
}

// ---------------------------------------------------------------------------
// metadata order: z [1024*128], W1 [256*128], b1 [128], W2 [128], b2 [1]
// output: float32 [1024*1024]
// ---------------------------------------------------------------------------
extern "C" void kernel_launch(void* const* d_in, const int* in_sizes, int n_in,
                              void* d_out, int out_size)
{
    const float* z  = (const float*)d_in[0];
    const float* W1 = (const float*)d_in[1];
    const float* b1 = (const float*)d_in[2];
    const float* W2 = (const float*)d_in[3];
    const float* b2 = (const float*)d_in[4];
    float* out = (float*)d_out;

    const int smem_bytes = 2 * DD * TPAD * sizeof(float)
                         + DD * sizeof(unsigned long long);
    cudaFuncSetAttribute(pair_kernel,
                         cudaFuncAttributeMaxDynamicSharedMemorySize, smem_bytes);

    prep_kernel<<<NN / 8, 512>>>(z, W1, b1, W2);

    dim3 blk(16, 16);
    dim3 grd(NN / 64, NN / 64);
    pair_kernel<<<grd, blk, smem_bytes>>>(b2, out);
}